// round 14
// baseline (speedup 1.0000x reference)
#include <cuda_runtime.h>
#include <cuda_fp16.h>
#include <cstdint>

// ---------------- problem constants ----------------
#define HH 80
#define WW 120
#define TT 12
#define FF 32
#define NPX (HH*WW)

#define TILY 20
#define TILX 8
#define NTILES 60        // (80/20) * (120/8)
#define NTHREADS 640     // 20 warps: 10 row-groups (5/batch) x 2 n-slices

#define HROWS 22
#define HCOLS 10
#define NHALO 220        // halo pixels per batch
#define PXB 208          // pixel stride bytes: [h 32f16 (64B) | xim 64f16 (128B) | pad 16B]

#define NKS 22           // ksteps: 18 h (9 taps x 2) + 4 xim
#define KW 360           // f16 per weight row: h 288 + xim 54 + pad
#define WRB 720          // weight row stride bytes (conflict-free)

#define SM_HALO_B (2*NHALO*PXB)   // 91520
#define SM_WA_B   (64*WRB)        // 46080
#define SM_WB_B   (32*WRB)        // 23040

// ---------------- global scratch ----------------
__device__ __half g_wAh[2*64*KW];
__device__ __half g_wBh[2*32*KW];
__device__ float  g_h  [2*2*NPX*FF];       // fp32 state (exact bypass)
__device__ float  g_z  [2*2*NPX*FF];       // fp32 update gate
__device__ __half g_hf [2*2*NPX*FF];       // f16 mirror (conv operand)
__device__ __half g_rhf[2*2*NPX*FF];       // f16 r*h (conv operand)
__device__ __half g_xim[(size_t)2*TT*NPX*64];  // x im2col: 9 taps x 6 ch + pad

// ---------------- helpers ----------------
__device__ __forceinline__ uint32_t smem_u32(const void* p) {
    uint32_t a;
    asm("{ .reg .u64 t; cvta.to.shared.u64 t, %1; cvt.u32.u64 %0, t; }" : "=r"(a) : "l"(p));
    return a;
}
__device__ __forceinline__ float sigm(float v) {
    return __fdividef(1.0f, 1.0f + __expf(-v));
}
__device__ __forceinline__ float ftanh(float v) {
    float e = __expf(-2.0f * v);
    return __fdividef(1.0f - e, 1.0f + e);
}
__device__ __forceinline__ void ldm_x4(uint32_t& r0, uint32_t& r1, uint32_t& r2, uint32_t& r3,
                                       uint32_t addr) {
    asm volatile("ldmatrix.sync.aligned.m8n8.x4.shared.b16 {%0,%1,%2,%3}, [%4];"
                 : "=r"(r0), "=r"(r1), "=r"(r2), "=r"(r3) : "r"(addr));
}
__device__ __forceinline__ void mma16816(float* c,
                                         uint32_t a0, uint32_t a1, uint32_t a2, uint32_t a3,
                                         uint32_t b0, uint32_t b1) {
    asm volatile("mma.sync.aligned.m16n8k16.row.col.f32.f16.f16.f32 "
                 "{%0,%1,%2,%3}, {%4,%5,%6,%7}, {%8,%9}, {%0,%1,%2,%3};"
                 : "+f"(c[0]), "+f"(c[1]), "+f"(c[2]), "+f"(c[3])
                 : "r"(a0), "r"(a1), "r"(a2), "r"(a3), "r"(b0), "r"(b1));
}

// kstep -> A-fragment byte offset from the top-left halo pixel base
__device__ __forceinline__ uint32_t kstep_a_off(int kk) {
    if (kk < 18) {
        const int tap = kk >> 1, ch = kk & 1;
        const int ky = tap / 3, kx = tap - ky*3;
        return (uint32_t)((ky*HCOLS + kx)*PXB + ch*32);
    }
    return (uint32_t)((HCOLS + 1)*PXB + 64 + (kk - 18)*32);   // center pixel xim block
}

// ---------------- one-time packs ----------------
// weight row n, k: [h: tap*32+c (288) | xim: 288 + tap*6+cx (54) | pad]
__global__ void pack_kernel(const float* __restrict__ WxF, const float* __restrict__ WzrF,
                            const float* __restrict__ WhF,
                            const float* __restrict__ WxB, const float* __restrict__ WzrB,
                            const float* __restrict__ WhB)
{
    const int TOT = 2*96*KW;
    for (int i = blockIdx.x*blockDim.x + threadIdx.x; i < TOT; i += gridDim.x*blockDim.x) {
        int dir = i / (96*KW); int r = i - dir*(96*KW);
        int n96 = r / KW;      int k = r - n96*KW;
        const float* Wx  = dir ? WxB  : WxF;
        const float* Wzr = dir ? WzrB : WzrF;
        const float* Wh  = dir ? WhB  : WhF;
        float v = 0.0f;
        if (k < 288) {
            int tap = k / 32, c = k - tap*32;
            if (n96 < 64) v = Wzr[(tap*32 + c)*64 + n96];
            else          v = Wh [(tap*32 + c)*32 + (n96 - 64)];
        } else if (k < 342) {
            int j = k - 288;
            int tap = j / 6, cx = j - tap*6;
            v = Wx[(tap*6 + cx)*96 + n96];
        }
        __half hv = __float2half_rn(v);
        if (n96 < 64) g_wAh[(dir*64 + n96)*KW + k]        = hv;
        else          g_wBh[(dir*32 + (n96 - 64))*KW + k] = hv;
    }
}

// im2col of x into f16: per pixel 64 f16 = [tap*6+cx (54) | zeros]
__global__ void build_xim(const float* __restrict__ x) {
    const int n = 2*TT*NPX;
    for (int p = blockIdx.x*blockDim.x + threadIdx.x; p < n; p += gridDim.x*blockDim.x) {
        const int bt = p / NPX, px = p - bt*NPX;
        const int gy = px / WW, gx = px - gy*WW;
        uint32_t u[32];
        __half* hw = (__half*)u;
        #pragma unroll
        for (int i = 0; i < 64; ++i) hw[i] = __ushort_as_half(0);
        #pragma unroll
        for (int tap = 0; tap < 9; ++tap) {
            const int ky = tap / 3, kx = tap - ky*3;
            const int iy = gy + ky - 1, ix = gx + kx - 1;
            if (iy >= 0 && iy < HH && ix >= 0 && ix < WW) {
                const float* sp = x + ((size_t)bt*NPX + iy*WW + ix)*6;
                #pragma unroll
                for (int c = 0; c < 6; ++c) hw[tap*6 + c] = __float2half_rn(sp[c]);
            }
        }
        uint4* dst = (uint4*)(g_xim + (size_t)p*64);
        #pragma unroll
        for (int j = 0; j < 8; ++j)
            dst[j] = make_uint4(u[4*j], u[4*j+1], u[4*j+2], u[4*j+3]);
    }
}

__global__ void zero_h_kernel() {
    const int n = 2*2*NPX*FF;
    for (int i = blockIdx.x*blockDim.x + threadIdx.x; i < n; i += gridDim.x*blockDim.x) {
        g_h[i] = 0.0f;
        if (i < n/2) ((uint32_t*)g_hf)[i] = 0u;
    }
}

// ---------------- halo staging: h (4x16B) + xim (8x16B) per pixel ----------------
__device__ __forceinline__ void stage_halo(char* sHalo, const __half* __restrict__ stf,
                                           int dir, int t, int ty0, int tx0, int tid)
{
    if (tid < 2*NHALO) {
        const int hb  = tid / NHALO;
        const int hpx = tid - hb*NHALO;
        const int sy = hpx / HCOLS, sx = hpx - sy*HCOLS;
        const int gy = ty0 + sy - 1, gx = tx0 + sx - 1;
        uint4* dst = (uint4*)(sHalo + tid*PXB);
        if (gy >= 0 && gy < HH && gx >= 0 && gx < WW) {
            const uint4* hs = (const uint4*)(stf + (size_t)((dir*2 + hb)*NPX + gy*WW + gx)*FF);
            dst[0] = hs[0]; dst[1] = hs[1]; dst[2] = hs[2]; dst[3] = hs[3];
            const uint4* xi = (const uint4*)(g_xim + (size_t)((hb*TT + t)*NPX + gy*WW + gx)*64);
            #pragma unroll
            for (int j = 0; j < 8; ++j) dst[4 + j] = xi[j];
        } else {
            uint4 z = make_uint4(0u,0u,0u,0u);
            #pragma unroll
            for (int j = 0; j < 12; ++j) dst[j] = z;
        }
    }
}

// ---------------- Kernel A: gates (pipelined, r32 x n32 per warp) ----------------
__global__ void __launch_bounds__(NTHREADS, 1)
stepA(const float* __restrict__ bF, const float* __restrict__ bB, int s)
{
    extern __shared__ char smc[];
    char* sHalo = smc;
    char* sW    = smc + SM_HALO_B;

    const int dir = blockIdx.y, tile = blockIdx.x;
    const int ty0 = (tile / 15) * TILY, tx0 = (tile % 15) * TILX;
    const int t   = dir ? (TT - 1 - s) : s;
    const int tid = threadIdx.x;
    const float* bias = dir ? bB : bF;

    {
        const uint4* src = (const uint4*)(g_wAh + (size_t)dir*64*KW);
        uint4* dst = (uint4*)sW;
        for (int i = tid; i < SM_WA_B/16; i += NTHREADS) dst[i] = src[i];
    }
    stage_halo(sHalo, g_hf, dir, t, ty0, tx0, tid);
    __syncthreads();

    const int warp = tid >> 5, lane = tid & 31;
    const int rg5 = warp % 10;           // row-group (5 per batch)
    const int nh  = warp / 10;           // n-slice: 0 -> z, 1 -> r
    const int wb  = rg5 / 5;             // batch
    const int rgl = rg5 % 5;
    const uint32_t haloB = smem_u32(sHalo) + (uint32_t)(wb*NHALO*PXB);
    const uint32_t aHalf = (uint32_t)((lane >> 4) << 4);

    uint32_t rb[2];
    #pragma unroll
    for (int si = 0; si < 2; ++si) {
        int r  = lane & 15;
        int py = 4*rgl + 2*si + (r >> 3);
        int px = r & 7;
        rb[si] = haloB + (uint32_t)((py*HCOLS + px)*PXB) + aHalf;
    }
    const uint32_t wB0 = smem_u32(sW);
    uint32_t bt[2];
    #pragma unroll
    for (int jp = 0; jp < 2; ++jp)
        bt[jp] = wB0 + (uint32_t)(((nh*32 + jp*16 + (lane>>4)*8 + (lane&7))*WRB))
                     + (uint32_t)(((lane>>3)&1) << 4);

    float C[2][4][4];
    #pragma unroll
    for (int si = 0; si < 2; ++si)
        #pragma unroll
        for (int j = 0; j < 4; ++j)
            C[si][j][0]=C[si][j][1]=C[si][j][2]=C[si][j][3]=0.0f;

    uint32_t Af[2][2][4], Bf[2][2][4];
    ldm_x4(Af[0][0][0],Af[0][0][1],Af[0][0][2],Af[0][0][3], rb[0] + kstep_a_off(0));
    ldm_x4(Af[0][1][0],Af[0][1][1],Af[0][1][2],Af[0][1][3], rb[1] + kstep_a_off(0));
    ldm_x4(Bf[0][0][0],Bf[0][0][1],Bf[0][0][2],Bf[0][0][3], bt[0]);
    ldm_x4(Bf[0][1][0],Bf[0][1][1],Bf[0][1][2],Bf[0][1][3], bt[1]);

    #pragma unroll
    for (int kk = 0; kk < NKS; ++kk) {
        const int cur = kk & 1, nxt = cur ^ 1;
        if (kk < NKS - 1) {
            const uint32_t po = kstep_a_off(kk + 1);
            const uint32_t wo = (uint32_t)((kk + 1)*32);
            ldm_x4(Af[nxt][0][0],Af[nxt][0][1],Af[nxt][0][2],Af[nxt][0][3], rb[0] + po);
            ldm_x4(Af[nxt][1][0],Af[nxt][1][1],Af[nxt][1][2],Af[nxt][1][3], rb[1] + po);
            ldm_x4(Bf[nxt][0][0],Bf[nxt][0][1],Bf[nxt][0][2],Bf[nxt][0][3], bt[0] + wo);
            ldm_x4(Bf[nxt][1][0],Bf[nxt][1][1],Bf[nxt][1][2],Bf[nxt][1][3], bt[1] + wo);
        }
        #pragma unroll
        for (int si = 0; si < 2; ++si)
            #pragma unroll
            for (int jp = 0; jp < 2; ++jp) {
                mma16816(C[si][2*jp],
                         Af[cur][si][0],Af[cur][si][1],Af[cur][si][2],Af[cur][si][3],
                         Bf[cur][jp][0],Bf[cur][jp][1]);
                mma16816(C[si][2*jp+1],
                         Af[cur][si][0],Af[cur][si][1],Af[cur][si][2],Af[cur][si][3],
                         Bf[cur][jp][2],Bf[cur][jp][3]);
            }
    }

    // epilogue: nh=0 -> z (fp32), nh=1 -> r*h (f16 mirror)
    const int fc  = (lane & 3) * 2;
    const int pxe = lane >> 2;
    const size_t sob = (size_t)(dir*2 + wb)*NPX*FF;
    #pragma unroll
    for (int si = 0; si < 2; ++si)
    #pragma unroll
    for (int cc = 0; cc < 2; ++cc) {
        const int py = 4*rgl + 2*si + cc;
        const int gy = ty0 + py, gx = tx0 + pxe;
        const size_t pb = sob + (size_t)(gy*WW + gx)*FF;
        if (nh == 0) {
            #pragma unroll
            for (int j = 0; j < 4; ++j) {
                const int n = j*8 + fc;
                float v0 = sigm(C[si][j][2*cc]   + __ldg(bias + n));
                float v1 = sigm(C[si][j][2*cc+1] + __ldg(bias + n + 1));
                *(float2*)(g_z + pb + n) = make_float2(v0, v1);
            }
        } else {
            const char* hpx = sHalo + (size_t)(wb*NHALO + (py+1)*HCOLS + (pxe+1))*PXB;
            #pragma unroll
            for (int j = 0; j < 4; ++j) {
                const int n = j*8 + fc;
                float r0 = sigm(C[si][j][2*cc]   + __ldg(bias + 32 + n));
                float r1 = sigm(C[si][j][2*cc+1] + __ldg(bias + 32 + n + 1));
                float2 hv = __half22float2(*(const __half2*)(hpx + n*2));
                *(__half2*)(g_rhf + pb + n) = __floats2half2_rn(r0*hv.x, r1*hv.y);
            }
        }
    }
}

// ---------------- Kernel B: candidate + GRU update (pipelined, r32 x n16) ----------
__global__ void __launch_bounds__(NTHREADS, 1)
stepB(const float* __restrict__ bF, const float* __restrict__ bB,
      float* __restrict__ out, int s)
{
    extern __shared__ char smc[];
    char* sHalo = smc;
    char* sW    = smc + SM_HALO_B;

    const int dir = blockIdx.y, tile = blockIdx.x;
    const int ty0 = (tile / 15) * TILY, tx0 = (tile % 15) * TILX;
    const int t   = dir ? (TT - 1 - s) : s;
    const int tid = threadIdx.x;
    const float* bias = dir ? bB : bF;

    {
        const uint4* src = (const uint4*)(g_wBh + (size_t)dir*32*KW);
        uint4* dst = (uint4*)sW;
        for (int i = tid; i < SM_WB_B/16; i += NTHREADS) dst[i] = src[i];
    }
    stage_halo(sHalo, g_rhf, dir, t, ty0, tx0, tid);
    __syncthreads();

    const int warp = tid >> 5, lane = tid & 31;
    const int rg5 = warp % 10;
    const int nh  = warp / 10;           // n-slice: channels [nh*16, nh*16+16)
    const int wb  = rg5 / 5;
    const int rgl = rg5 % 5;
    const uint32_t haloB = smem_u32(sHalo) + (uint32_t)(wb*NHALO*PXB);
    const uint32_t aHalf = (uint32_t)((lane >> 4) << 4);

    uint32_t rb[2];
    #pragma unroll
    for (int si = 0; si < 2; ++si) {
        int r  = lane & 15;
        int py = 4*rgl + 2*si + (r >> 3);
        int px = r & 7;
        rb[si] = haloB + (uint32_t)((py*HCOLS + px)*PXB) + aHalf;
    }
    const uint32_t wB0 = smem_u32(sW);
    const uint32_t bt = wB0 + (uint32_t)(((nh*16 + (lane>>4)*8 + (lane&7))*WRB))
                           + (uint32_t)(((lane>>3)&1) << 4);

    float C[2][2][4];
    #pragma unroll
    for (int si = 0; si < 2; ++si)
        #pragma unroll
        for (int j = 0; j < 2; ++j)
            C[si][j][0]=C[si][j][1]=C[si][j][2]=C[si][j][3]=0.0f;

    uint32_t Af[2][2][4], Bf[2][4];
    ldm_x4(Af[0][0][0],Af[0][0][1],Af[0][0][2],Af[0][0][3], rb[0] + kstep_a_off(0));
    ldm_x4(Af[0][1][0],Af[0][1][1],Af[0][1][2],Af[0][1][3], rb[1] + kstep_a_off(0));
    ldm_x4(Bf[0][0],Bf[0][1],Bf[0][2],Bf[0][3], bt);

    #pragma unroll
    for (int kk = 0; kk < NKS; ++kk) {
        const int cur = kk & 1, nxt = cur ^ 1;
        if (kk < NKS - 1) {
            const uint32_t po = kstep_a_off(kk + 1);
            const uint32_t wo = (uint32_t)((kk + 1)*32);
            ldm_x4(Af[nxt][0][0],Af[nxt][0][1],Af[nxt][0][2],Af[nxt][0][3], rb[0] + po);
            ldm_x4(Af[nxt][1][0],Af[nxt][1][1],Af[nxt][1][2],Af[nxt][1][3], rb[1] + po);
            ldm_x4(Bf[nxt][0],Bf[nxt][1],Bf[nxt][2],Bf[nxt][3], bt + wo);
        }
        #pragma unroll
        for (int si = 0; si < 2; ++si) {
            mma16816(C[si][0],
                     Af[cur][si][0],Af[cur][si][1],Af[cur][si][2],Af[cur][si][3],
                     Bf[cur][0],Bf[cur][1]);
            mma16816(C[si][1],
                     Af[cur][si][0],Af[cur][si][1],Af[cur][si][2],Af[cur][si][3],
                     Bf[cur][2],Bf[cur][3]);
        }
    }

    // epilogue: GRU update
    const int fc  = (lane & 3) * 2;
    const int pxe = lane >> 2;
    const size_t sob = (size_t)(dir*2 + wb)*NPX*FF;
    #pragma unroll
    for (int si = 0; si < 2; ++si)
    #pragma unroll
    for (int cc = 0; cc < 2; ++cc) {
        const int py = 4*rgl + 2*si + cc;
        const int gy = ty0 + py, gx = tx0 + pxe;
        const size_t pb = sob + (size_t)(gy*WW + gx)*FF;
        float* op = out + ((size_t)((wb*TT + t)*HH + gy)*WW + gx)*64 + dir*32;
        #pragma unroll
        for (int j = 0; j < 2; ++j) {
            const int n = nh*16 + j*8 + fc;
            float2 z = *(const float2*)(g_z + pb + n);
            float2 h = *(const float2*)(g_h + pb + n);
            float hh0 = ftanh(C[si][j][2*cc]   + __ldg(bias + 64 + n));
            float hh1 = ftanh(C[si][j][2*cc+1] + __ldg(bias + 64 + n + 1));
            float2 hn = make_float2(z.x*h.x + (1.0f - z.x)*hh0,
                                    z.y*h.y + (1.0f - z.y)*hh1);
            *(float2*)(g_h + pb + n)   = hn;
            *(__half2*)(g_hf + pb + n) = __floats2half2_rn(hn.x, hn.y);
            *(float2*)(op + n)         = hn;
        }
    }
}

extern "C" void kernel_launch(void* const* d_in, const int* in_sizes, int n_in,
                              void* d_out, int out_size)
{
    const float* x    = (const float*)d_in[0];
    const float* WxF  = (const float*)d_in[1];
    const float* bF   = (const float*)d_in[2];
    const float* WzrF = (const float*)d_in[3];
    const float* WhF  = (const float*)d_in[4];
    const float* WxB  = (const float*)d_in[5];
    const float* bB   = (const float*)d_in[6];
    const float* WzrB = (const float*)d_in[7];
    const float* WhB  = (const float*)d_in[8];
    float* out = (float*)d_out;

    const int smA = SM_HALO_B + SM_WA_B;   // 137600 B
    const int smB = SM_HALO_B + SM_WB_B;   // 114560 B
    cudaFuncSetAttribute(stepA, cudaFuncAttributeMaxDynamicSharedMemorySize, smA);
    cudaFuncSetAttribute(stepB, cudaFuncAttributeMaxDynamicSharedMemorySize, smB);

    pack_kernel<<<96, 256>>>(WxF, WzrF, WhF, WxB, WzrB, WhB);
    build_xim<<<256, 256>>>(x);
    zero_h_kernel<<<256, 256>>>();

    dim3 grid(NTILES, 2);   // 60 tiles x 2 dir = 120 blocks (single wave, 1/SM)
    for (int s = 0; s < TT; ++s) {
        stepA<<<grid, NTHREADS, smA>>>(bF, bB, s);
        stepB<<<grid, NTHREADS, smB>>>(bF, bB, out, s);
    }
}

// round 15
// speedup vs baseline: 1.0707x; 1.0707x over previous
#include <cuda_runtime.h>
#include <cuda_fp16.h>
#include <cstdint>

// ---------------- problem constants ----------------
#define HH 80
#define WW 120
#define TT 12
#define FF 32
#define NPX (HH*WW)

#define TILY 20
#define TILX 8
#define NTILES 60        // (80/20) * (120/8)
#define NTHREADS 640     // 20 warps: 10 row-groups (5/batch) x 2 n-slices

#define HROWS 22
#define HCOLS 10
#define NHALO 220        // halo pixels per batch
#define PXB 112          // pixel stride bytes: [h 32f16 | x 8f16 | pad]

#define KW 440           // f16 per weight row (432 = 9*48 + pad)
#define WRB 880

#define SM_HALO_B (2*NHALO*PXB)   // 49280
#define SM_WA_B   (64*WRB)        // 56320
#define SM_WB_B   (32*WRB)        // 28160

// ---------------- global scratch ----------------
__device__ __half g_wAh[2*64*KW];
__device__ __half g_wBh[2*32*KW];
__device__ float  g_h  [2*2*NPX*FF];     // fp32 state (exact bypass)
__device__ float  g_z  [2*2*NPX*FF];     // fp32 update gate
__device__ __half g_hf [2*2*NPX*FF];     // f16 mirror (conv operand)
__device__ __half g_rhf[2*2*NPX*FF];     // f16 r*h (conv operand)
__device__ __half g_xf8[2*TT*NPX*8];     // x preconverted (6 + 2 zeros)

// ---------------- helpers ----------------
__device__ __forceinline__ uint32_t smem_u32(const void* p) {
    uint32_t a;
    asm("{ .reg .u64 t; cvta.to.shared.u64 t, %1; cvt.u32.u64 %0, t; }" : "=r"(a) : "l"(p));
    return a;
}
__device__ __forceinline__ float sigm(float v) {
    return __fdividef(1.0f, 1.0f + __expf(-v));
}
__device__ __forceinline__ float ftanh(float v) {
    float e = __expf(-2.0f * v);
    return __fdividef(1.0f - e, 1.0f + e);
}
__device__ __forceinline__ void ldm_x4(uint32_t& r0, uint32_t& r1, uint32_t& r2, uint32_t& r3,
                                       uint32_t addr) {
    asm volatile("ldmatrix.sync.aligned.m8n8.x4.shared.b16 {%0,%1,%2,%3}, [%4];"
                 : "=r"(r0), "=r"(r1), "=r"(r2), "=r"(r3) : "r"(addr));
}
__device__ __forceinline__ void mma16816(float* c,
                                         uint32_t a0, uint32_t a1, uint32_t a2, uint32_t a3,
                                         uint32_t b0, uint32_t b1) {
    asm volatile("mma.sync.aligned.m16n8k16.row.col.f32.f16.f16.f32 "
                 "{%0,%1,%2,%3}, {%4,%5,%6,%7}, {%8,%9}, {%0,%1,%2,%3};"
                 : "+f"(c[0]), "+f"(c[1]), "+f"(c[2]), "+f"(c[3])
                 : "r"(a0), "r"(a1), "r"(a2), "r"(a3), "r"(b0), "r"(b1));
}

// ---------------- merged one-time prologue (weights + x convert + state zero) ------
__global__ void init_kernel(const float* __restrict__ x,
                            const float* __restrict__ WxF, const float* __restrict__ WzrF,
                            const float* __restrict__ WhF,
                            const float* __restrict__ WxB, const float* __restrict__ WzrB,
                            const float* __restrict__ WhB)
{
    const int gstride = gridDim.x * blockDim.x;
    const int gtid = blockIdx.x*blockDim.x + threadIdx.x;

    // 1) weight pack: row n, k = tap*48 + c; c<32 = state ch, 32..37 = x ch, else 0
    {
        const int TOT = 2*96*KW;
        for (int i = gtid; i < TOT; i += gstride) {
            int dir = i / (96*KW); int r = i - dir*(96*KW);
            int n96 = r / KW;      int k = r - n96*KW;
            float v = 0.0f;
            if (k < 432) {
                int tap = k / 48, c = k - tap*48;
                const float* Wx  = dir ? WxB  : WxF;
                const float* Wzr = dir ? WzrB : WzrF;
                const float* Wh  = dir ? WhB  : WhF;
                if (c < 32) {
                    if (n96 < 64) v = Wzr[(tap*32 + c)*64 + n96];
                    else          v = Wh [(tap*32 + c)*32 + (n96 - 64)];
                } else if (c < 38) {
                    v = Wx[(tap*6 + (c - 32))*96 + n96];
                }
            }
            __half hv = __float2half_rn(v);
            if (n96 < 64) g_wAh[(dir*64 + n96)*KW + k]        = hv;
            else          g_wBh[(dir*32 + (n96 - 64))*KW + k] = hv;
        }
    }
    // 2) x -> f16x8 preconvert
    {
        const int n = 2*TT*NPX;
        for (int p = gtid; p < n; p += gstride) {
            const float* src = x + (size_t)p*6;
            __half2 h0 = __floats2half2_rn(src[0], src[1]);
            __half2 h1 = __floats2half2_rn(src[2], src[3]);
            __half2 h2 = __floats2half2_rn(src[4], src[5]);
            uint4 v;
            v.x = *(uint32_t*)&h0; v.y = *(uint32_t*)&h1; v.z = *(uint32_t*)&h2; v.w = 0u;
            *(uint4*)(g_xf8 + (size_t)p*8) = v;
        }
    }
    // 3) zero h (fp32) + hf (f16)
    {
        const int n = 2*2*NPX*FF;
        for (int i = gtid; i < n; i += gstride) {
            g_h[i] = 0.0f;
            if (i < n/2) ((uint32_t*)g_hf)[i] = 0u;
        }
    }
}

// ---------------- halo staging: 16B-granular, all threads ----------------
__device__ __forceinline__ void stage_halo(char* sHalo, const __half* __restrict__ stf,
                                           int dir, int t, int ty0, int tx0, int tid)
{
    for (int u = tid; u < 2*NHALO*7; u += NTHREADS) {
        const int p  = u / 7, j = u - p*7;
        const int hb = p / NHALO;
        const int hpx = p - hb*NHALO;
        const int sy = hpx / HCOLS, sx = hpx - sy*HCOLS;
        const int gy = ty0 + sy - 1, gx = tx0 + sx - 1;
        uint4 v = make_uint4(0u,0u,0u,0u);
        if (gy >= 0 && gy < HH && gx >= 0 && gx < WW) {
            if (j < 4)
                v = ((const uint4*)(stf + (size_t)((dir*2 + hb)*NPX + gy*WW + gx)*FF))[j];
            else if (j == 4)
                v = *(const uint4*)(g_xf8 + (size_t)((hb*TT + t)*NPX + gy*WW + gx)*8);
        }
        ((uint4*)(sHalo + p*PXB))[j] = v;
    }
}

// ---------------- Kernel A: gates (pipelined, r32 x n32 per warp) ----------------
__global__ void __launch_bounds__(NTHREADS, 1)
stepA(const float* __restrict__ bF, const float* __restrict__ bB, int s)
{
    extern __shared__ char smc[];
    char* sHalo = smc;
    char* sW    = smc + SM_HALO_B;

    const int dir = blockIdx.y, tile = blockIdx.x;
    const int ty0 = (tile / 15) * TILY, tx0 = (tile % 15) * TILX;
    const int t   = dir ? (TT - 1 - s) : s;
    const int tid = threadIdx.x;
    const float* bias = dir ? bB : bF;

    {
        const uint4* src = (const uint4*)(g_wAh + (size_t)dir*64*KW);
        uint4* dst = (uint4*)sW;
        for (int i = tid; i < SM_WA_B/16; i += NTHREADS) dst[i] = src[i];
    }
    stage_halo(sHalo, g_hf, dir, t, ty0, tx0, tid);
    __syncthreads();

    const int warp = tid >> 5, lane = tid & 31;
    const int rg5 = warp % 10;           // row-group (5 per batch)
    const int nh  = warp / 10;           // n-slice: 0 -> z, 1 -> r
    const int wb  = rg5 / 5;             // batch
    const int rgl = rg5 % 5;
    const uint32_t haloB = smem_u32(sHalo) + (uint32_t)(wb*NHALO*PXB);
    const uint32_t aHalf = (uint32_t)((lane >> 4) << 4);

    uint32_t rb[2];
    #pragma unroll
    for (int si = 0; si < 2; ++si) {
        int r  = lane & 15;
        int py = 4*rgl + 2*si + (r >> 3);
        int px = r & 7;
        rb[si] = haloB + (uint32_t)((py*HCOLS + px)*PXB) + aHalf;
    }
    const uint32_t wB0 = smem_u32(sW);
    uint32_t bt[2];
    #pragma unroll
    for (int jp = 0; jp < 2; ++jp)
        bt[jp] = wB0 + (uint32_t)(((nh*32 + jp*16 + (lane>>4)*8 + (lane&7))*WRB))
                     + (uint32_t)(((lane>>3)&1) << 4);

    float C[2][4][4];
    #pragma unroll
    for (int si = 0; si < 2; ++si)
        #pragma unroll
        for (int j = 0; j < 4; ++j)
            C[si][j][0]=C[si][j][1]=C[si][j][2]=C[si][j][3]=0.0f;

    uint32_t Af[2][2][4], Bf[2][2][4];
    ldm_x4(Af[0][0][0],Af[0][0][1],Af[0][0][2],Af[0][0][3], rb[0]);
    ldm_x4(Af[0][1][0],Af[0][1][1],Af[0][1][2],Af[0][1][3], rb[1]);
    ldm_x4(Bf[0][0][0],Bf[0][0][1],Bf[0][0][2],Bf[0][0][3], bt[0]);
    ldm_x4(Bf[0][1][0],Bf[0][1][1],Bf[0][1][2],Bf[0][1][3], bt[1]);

    #pragma unroll
    for (int kk = 0; kk < 27; ++kk) {
        const int cur = kk & 1, nxt = cur ^ 1;
        if (kk < 26) {
            const int k1  = kk + 1;
            const int tap = k1 / 3, ch = k1 - tap*3;
            const int ky  = tap / 3, kx = tap - ky*3;
            const uint32_t po = (uint32_t)((ky*HCOLS + kx)*PXB + ch*32);
            const uint32_t wo = (uint32_t)(tap*96 + ch*32);
            ldm_x4(Af[nxt][0][0],Af[nxt][0][1],Af[nxt][0][2],Af[nxt][0][3], rb[0] + po);
            ldm_x4(Af[nxt][1][0],Af[nxt][1][1],Af[nxt][1][2],Af[nxt][1][3], rb[1] + po);
            ldm_x4(Bf[nxt][0][0],Bf[nxt][0][1],Bf[nxt][0][2],Bf[nxt][0][3], bt[0] + wo);
            ldm_x4(Bf[nxt][1][0],Bf[nxt][1][1],Bf[nxt][1][2],Bf[nxt][1][3], bt[1] + wo);
        }
        #pragma unroll
        for (int si = 0; si < 2; ++si)
            #pragma unroll
            for (int jp = 0; jp < 2; ++jp) {
                mma16816(C[si][2*jp],
                         Af[cur][si][0],Af[cur][si][1],Af[cur][si][2],Af[cur][si][3],
                         Bf[cur][jp][0],Bf[cur][jp][1]);
                mma16816(C[si][2*jp+1],
                         Af[cur][si][0],Af[cur][si][1],Af[cur][si][2],Af[cur][si][3],
                         Bf[cur][jp][2],Bf[cur][jp][3]);
            }
    }

    // epilogue: nh=0 -> z (fp32), nh=1 -> r*h (f16 mirror)
    const int fc  = (lane & 3) * 2;
    const int pxe = lane >> 2;
    const size_t sob = (size_t)(dir*2 + wb)*NPX*FF;
    #pragma unroll
    for (int si = 0; si < 2; ++si)
    #pragma unroll
    for (int cc = 0; cc < 2; ++cc) {
        const int py = 4*rgl + 2*si + cc;
        const int gy = ty0 + py, gx = tx0 + pxe;
        const size_t pb = sob + (size_t)(gy*WW + gx)*FF;
        if (nh == 0) {
            #pragma unroll
            for (int j = 0; j < 4; ++j) {
                const int n = j*8 + fc;
                float v0 = sigm(C[si][j][2*cc]   + __ldg(bias + n));
                float v1 = sigm(C[si][j][2*cc+1] + __ldg(bias + n + 1));
                *(float2*)(g_z + pb + n) = make_float2(v0, v1);
            }
        } else {
            const char* hpx = sHalo + (size_t)(wb*NHALO + (py+1)*HCOLS + (pxe+1))*PXB;
            #pragma unroll
            for (int j = 0; j < 4; ++j) {
                const int n = j*8 + fc;
                float r0 = sigm(C[si][j][2*cc]   + __ldg(bias + 32 + n));
                float r1 = sigm(C[si][j][2*cc+1] + __ldg(bias + 32 + n + 1));
                float2 hv = __half22float2(*(const __half2*)(hpx + n*2));
                *(__half2*)(g_rhf + pb + n) = __floats2half2_rn(r0*hv.x, r1*hv.y);
            }
        }
    }
}

// ---------------- Kernel B: candidate + GRU update (pipelined, r32 x n16) ----------
__global__ void __launch_bounds__(NTHREADS, 1)
stepB(const float* __restrict__ bF, const float* __restrict__ bB,
      float* __restrict__ out, int s)
{
    extern __shared__ char smc[];
    char* sHalo = smc;
    char* sW    = smc + SM_HALO_B;

    const int dir = blockIdx.y, tile = blockIdx.x;
    const int ty0 = (tile / 15) * TILY, tx0 = (tile % 15) * TILX;
    const int t   = dir ? (TT - 1 - s) : s;
    const int tid = threadIdx.x;
    const float* bias = dir ? bB : bF;

    {
        const uint4* src = (const uint4*)(g_wBh + (size_t)dir*32*KW);
        uint4* dst = (uint4*)sW;
        for (int i = tid; i < SM_WB_B/16; i += NTHREADS) dst[i] = src[i];
    }
    stage_halo(sHalo, g_rhf, dir, t, ty0, tx0, tid);
    __syncthreads();

    const int warp = tid >> 5, lane = tid & 31;
    const int rg5 = warp % 10;
    const int nh  = warp / 10;           // n-slice: channels [nh*16, nh*16+16)
    const int wb  = rg5 / 5;
    const int rgl = rg5 % 5;
    const uint32_t haloB = smem_u32(sHalo) + (uint32_t)(wb*NHALO*PXB);
    const uint32_t aHalf = (uint32_t)((lane >> 4) << 4);

    uint32_t rb[2];
    #pragma unroll
    for (int si = 0; si < 2; ++si) {
        int r  = lane & 15;
        int py = 4*rgl + 2*si + (r >> 3);
        int px = r & 7;
        rb[si] = haloB + (uint32_t)((py*HCOLS + px)*PXB) + aHalf;
    }
    const uint32_t wB0 = smem_u32(sW);
    const uint32_t bt = wB0 + (uint32_t)(((nh*16 + (lane>>4)*8 + (lane&7))*WRB))
                           + (uint32_t)(((lane>>3)&1) << 4);

    float C[2][2][4];
    #pragma unroll
    for (int si = 0; si < 2; ++si)
        #pragma unroll
        for (int j = 0; j < 2; ++j)
            C[si][j][0]=C[si][j][1]=C[si][j][2]=C[si][j][3]=0.0f;

    uint32_t Af[2][2][4], Bf[2][4];
    ldm_x4(Af[0][0][0],Af[0][0][1],Af[0][0][2],Af[0][0][3], rb[0]);
    ldm_x4(Af[0][1][0],Af[0][1][1],Af[0][1][2],Af[0][1][3], rb[1]);
    ldm_x4(Bf[0][0],Bf[0][1],Bf[0][2],Bf[0][3], bt);

    #pragma unroll
    for (int kk = 0; kk < 27; ++kk) {
        const int cur = kk & 1, nxt = cur ^ 1;
        if (kk < 26) {
            const int k1  = kk + 1;
            const int tap = k1 / 3, ch = k1 - tap*3;
            const int ky  = tap / 3, kx = tap - ky*3;
            const uint32_t po = (uint32_t)((ky*HCOLS + kx)*PXB + ch*32);
            const uint32_t wo = (uint32_t)(tap*96 + ch*32);
            ldm_x4(Af[nxt][0][0],Af[nxt][0][1],Af[nxt][0][2],Af[nxt][0][3], rb[0] + po);
            ldm_x4(Af[nxt][1][0],Af[nxt][1][1],Af[nxt][1][2],Af[nxt][1][3], rb[1] + po);
            ldm_x4(Bf[nxt][0],Bf[nxt][1],Bf[nxt][2],Bf[nxt][3], bt + wo);
        }
        #pragma unroll
        for (int si = 0; si < 2; ++si) {
            mma16816(C[si][0],
                     Af[cur][si][0],Af[cur][si][1],Af[cur][si][2],Af[cur][si][3],
                     Bf[cur][0],Bf[cur][1]);
            mma16816(C[si][1],
                     Af[cur][si][0],Af[cur][si][1],Af[cur][si][2],Af[cur][si][3],
                     Bf[cur][2],Bf[cur][3]);
        }
    }

    // epilogue: GRU update
    const int fc  = (lane & 3) * 2;
    const int pxe = lane >> 2;
    const size_t sob = (size_t)(dir*2 + wb)*NPX*FF;
    #pragma unroll
    for (int si = 0; si < 2; ++si)
    #pragma unroll
    for (int cc = 0; cc < 2; ++cc) {
        const int py = 4*rgl + 2*si + cc;
        const int gy = ty0 + py, gx = tx0 + pxe;
        const size_t pb = sob + (size_t)(gy*WW + gx)*FF;
        float* op = out + ((size_t)((wb*TT + t)*HH + gy)*WW + gx)*64 + dir*32;
        #pragma unroll
        for (int j = 0; j < 2; ++j) {
            const int n = nh*16 + j*8 + fc;
            float2 z = *(const float2*)(g_z + pb + n);
            float2 h = *(const float2*)(g_h + pb + n);
            float hh0 = ftanh(C[si][j][2*cc]   + __ldg(bias + 64 + n));
            float hh1 = ftanh(C[si][j][2*cc+1] + __ldg(bias + 64 + n + 1));
            float2 hn = make_float2(z.x*h.x + (1.0f - z.x)*hh0,
                                    z.y*h.y + (1.0f - z.y)*hh1);
            *(float2*)(g_h + pb + n)   = hn;
            *(__half2*)(g_hf + pb + n) = __floats2half2_rn(hn.x, hn.y);
            *(float2*)(op + n)         = hn;
        }
    }
}

extern "C" void kernel_launch(void* const* d_in, const int* in_sizes, int n_in,
                              void* d_out, int out_size)
{
    const float* x    = (const float*)d_in[0];
    const float* WxF  = (const float*)d_in[1];
    const float* bF   = (const float*)d_in[2];
    const float* WzrF = (const float*)d_in[3];
    const float* WhF  = (const float*)d_in[4];
    const float* WxB  = (const float*)d_in[5];
    const float* bB   = (const float*)d_in[6];
    const float* WzrB = (const float*)d_in[7];
    const float* WhB  = (const float*)d_in[8];
    float* out = (float*)d_out;

    const int smA = SM_HALO_B + SM_WA_B;   // 105600 B
    const int smB = SM_HALO_B + SM_WB_B;   // 77440 B
    cudaFuncSetAttribute(stepA, cudaFuncAttributeMaxDynamicSharedMemorySize, smA);
    cudaFuncSetAttribute(stepB, cudaFuncAttributeMaxDynamicSharedMemorySize, smB);

    init_kernel<<<148, 512>>>(x, WxF, WzrF, WhF, WxB, WzrB, WhB);

    dim3 grid(NTILES, 2);   // 60 tiles x 2 dir = 120 blocks (single wave, 1/SM)
    for (int s = 0; s < TT; ++s) {
        stepA<<<grid, NTHREADS, smA>>>(bF, bB, s);
        stepB<<<grid, NTHREADS, smB>>>(bF, bB, out, s);
    }
}

// round 16
// speedup vs baseline: 1.1964x; 1.1174x over previous
#include <cuda_runtime.h>
#include <cuda_fp16.h>
#include <cstdint>

// ---------------- problem constants ----------------
#define HH 80
#define WW 120
#define TT 12
#define FF 32
#define NPX (HH*WW)

#define TILY 20
#define TILX 8
#define NTILES 60        // (80/20) * (120/8)
#define NTHREADS 640     // 20 warps: 10 row-groups (5/batch) x 2 n-slices

#define HROWS 22
#define HCOLS 10
#define NHALO 220        // halo pixels per batch
#define PXB 112          // pixel stride bytes: [h 32f16 | x 8f16 | pad]

#define KW 440           // f16 per weight row (432 = 9*48 + pad)
#define WRB 880

#define SM_HALO_B (2*NHALO*PXB)   // 49280
#define SM_WA_B   (64*WRB)        // 56320
#define SM_WB_B   (32*WRB)        // 28160

// ---------------- global scratch ----------------
__device__ __half g_wAh[2*64*KW];
__device__ __half g_wBh[2*32*KW];
__device__ float  g_h  [2*2*NPX*FF];     // fp32 state (exact bypass)
__device__ float  g_z  [2*2*NPX*FF];     // fp32 update gate
__device__ __half g_hf [2*2*NPX*FF];     // f16 mirror (conv operand)
__device__ __half g_rhf[2*2*NPX*FF];     // f16 r*h (conv operand)
__device__ __half g_xf8[2*TT*NPX*8];     // x preconverted (6 + 2 zeros)

// ---------------- helpers ----------------
__device__ __forceinline__ uint32_t smem_u32(const void* p) {
    uint32_t a;
    asm("{ .reg .u64 t; cvta.to.shared.u64 t, %1; cvt.u32.u64 %0, t; }" : "=r"(a) : "l"(p));
    return a;
}
__device__ __forceinline__ float sigm(float v) {
    return __fdividef(1.0f, 1.0f + __expf(-v));
}
__device__ __forceinline__ float ftanh(float v) {
    float e = __expf(-2.0f * v);
    return __fdividef(1.0f - e, 1.0f + e);
}
__device__ __forceinline__ void ldm_x4(uint32_t& r0, uint32_t& r1, uint32_t& r2, uint32_t& r3,
                                       uint32_t addr) {
    asm volatile("ldmatrix.sync.aligned.m8n8.x4.shared.b16 {%0,%1,%2,%3}, [%4];"
                 : "=r"(r0), "=r"(r1), "=r"(r2), "=r"(r3) : "r"(addr));
}
__device__ __forceinline__ void mma16816(float* c,
                                         uint32_t a0, uint32_t a1, uint32_t a2, uint32_t a3,
                                         uint32_t b0, uint32_t b1) {
    asm volatile("mma.sync.aligned.m16n8k16.row.col.f32.f16.f16.f32 "
                 "{%0,%1,%2,%3}, {%4,%5,%6,%7}, {%8,%9}, {%0,%1,%2,%3};"
                 : "+f"(c[0]), "+f"(c[1]), "+f"(c[2]), "+f"(c[3])
                 : "r"(a0), "r"(a1), "r"(a2), "r"(a3), "r"(b0), "r"(b1));
}

// ---------------- merged one-time prologue (weights + x convert + state zero) ------
__global__ void init_kernel(const float* __restrict__ x,
                            const float* __restrict__ WxF, const float* __restrict__ WzrF,
                            const float* __restrict__ WhF,
                            const float* __restrict__ WxB, const float* __restrict__ WzrB,
                            const float* __restrict__ WhB)
{
    const int gstride = gridDim.x * blockDim.x;
    const int gtid = blockIdx.x*blockDim.x + threadIdx.x;

    // 1) weight pack: row n, k = tap*48 + c; c<32 = state ch, 32..37 = x ch, else 0
    {
        const int TOT = 2*96*KW;
        for (int i = gtid; i < TOT; i += gstride) {
            int dir = i / (96*KW); int r = i - dir*(96*KW);
            int n96 = r / KW;      int k = r - n96*KW;
            float v = 0.0f;
            if (k < 432) {
                int tap = k / 48, c = k - tap*48;
                const float* Wx  = dir ? WxB  : WxF;
                const float* Wzr = dir ? WzrB : WzrF;
                const float* Wh  = dir ? WhB  : WhF;
                if (c < 32) {
                    if (n96 < 64) v = Wzr[(tap*32 + c)*64 + n96];
                    else          v = Wh [(tap*32 + c)*32 + (n96 - 64)];
                } else if (c < 38) {
                    v = Wx[(tap*6 + (c - 32))*96 + n96];
                }
            }
            __half hv = __float2half_rn(v);
            if (n96 < 64) g_wAh[(dir*64 + n96)*KW + k]        = hv;
            else          g_wBh[(dir*32 + (n96 - 64))*KW + k] = hv;
        }
    }
    // 2) x -> f16x8 preconvert
    {
        const int n = 2*TT*NPX;
        for (int p = gtid; p < n; p += gstride) {
            const float* src = x + (size_t)p*6;
            __half2 h0 = __floats2half2_rn(src[0], src[1]);
            __half2 h1 = __floats2half2_rn(src[2], src[3]);
            __half2 h2 = __floats2half2_rn(src[4], src[5]);
            uint4 v;
            v.x = *(uint32_t*)&h0; v.y = *(uint32_t*)&h1; v.z = *(uint32_t*)&h2; v.w = 0u;
            *(uint4*)(g_xf8 + (size_t)p*8) = v;
        }
    }
    // 3) zero h (fp32) + hf (f16)
    {
        const int n = 2*2*NPX*FF;
        for (int i = gtid; i < n; i += gstride) {
            g_h[i] = 0.0f;
            if (i < n/2) ((uint32_t*)g_hf)[i] = 0u;
        }
    }
}

// ---------------- halo staging: per-pixel, aligned f16 copies (R11 form) ----------
__device__ __forceinline__ void stage_halo(char* sHalo, const __half* __restrict__ stf,
                                           int dir, int t, int ty0, int tx0, int tid)
{
    if (tid < 2*NHALO) {
        const int hb  = tid / NHALO;
        const int hpx = tid - hb*NHALO;
        const int sy = hpx / HCOLS, sx = hpx - sy*HCOLS;
        const int gy = ty0 + sy - 1, gx = tx0 + sx - 1;
        uint4* dst = (uint4*)(sHalo + tid*PXB);
        if (gy >= 0 && gy < HH && gx >= 0 && gx < WW) {
            const uint4* hs = (const uint4*)(stf + (size_t)((dir*2 + hb)*NPX + gy*WW + gx)*FF);
            dst[0] = hs[0]; dst[1] = hs[1]; dst[2] = hs[2]; dst[3] = hs[3];
            dst[4] = *(const uint4*)(g_xf8 + (size_t)((hb*TT + t)*NPX + gy*WW + gx)*8);
            dst[5] = make_uint4(0u,0u,0u,0u);
            dst[6] = make_uint4(0u,0u,0u,0u);
        } else {
            uint4 z = make_uint4(0u,0u,0u,0u);
            #pragma unroll
            for (int j = 0; j < 7; ++j) dst[j] = z;
        }
    }
}

// ---------------- Kernel A: gates (pipelined, r32 x n32 per warp) ----------------
__global__ void __launch_bounds__(NTHREADS, 1)
stepA(const float* __restrict__ bF, const float* __restrict__ bB, int s)
{
    extern __shared__ char smc[];
    char* sHalo = smc;
    char* sW    = smc + SM_HALO_B;

    const int dir = blockIdx.y, tile = blockIdx.x;
    const int ty0 = (tile / 15) * TILY, tx0 = (tile % 15) * TILX;
    const int t   = dir ? (TT - 1 - s) : s;
    const int tid = threadIdx.x;
    const float* bias = dir ? bB : bF;

    {
        const uint4* src = (const uint4*)(g_wAh + (size_t)dir*64*KW);
        uint4* dst = (uint4*)sW;
        for (int i = tid; i < SM_WA_B/16; i += NTHREADS) dst[i] = src[i];
    }
    stage_halo(sHalo, g_hf, dir, t, ty0, tx0, tid);
    __syncthreads();

    const int warp = tid >> 5, lane = tid & 31;
    const int rg5 = warp % 10;           // row-group (5 per batch)
    const int nh  = warp / 10;           // n-slice: 0 -> z, 1 -> r
    const int wb  = rg5 / 5;             // batch
    const int rgl = rg5 % 5;
    const uint32_t haloB = smem_u32(sHalo) + (uint32_t)(wb*NHALO*PXB);
    const uint32_t aHalf = (uint32_t)((lane >> 4) << 4);

    uint32_t rb[2];
    #pragma unroll
    for (int si = 0; si < 2; ++si) {
        int r  = lane & 15;
        int py = 4*rgl + 2*si + (r >> 3);
        int px = r & 7;
        rb[si] = haloB + (uint32_t)((py*HCOLS + px)*PXB) + aHalf;
    }
    const uint32_t wB0 = smem_u32(sW);
    uint32_t bt[2];
    #pragma unroll
    for (int jp = 0; jp < 2; ++jp)
        bt[jp] = wB0 + (uint32_t)(((nh*32 + jp*16 + (lane>>4)*8 + (lane&7))*WRB))
                     + (uint32_t)(((lane>>3)&1) << 4);

    float C[2][4][4];
    #pragma unroll
    for (int si = 0; si < 2; ++si)
        #pragma unroll
        for (int j = 0; j < 4; ++j)
            C[si][j][0]=C[si][j][1]=C[si][j][2]=C[si][j][3]=0.0f;

    uint32_t Af[2][2][4], Bf[2][2][4];
    ldm_x4(Af[0][0][0],Af[0][0][1],Af[0][0][2],Af[0][0][3], rb[0]);
    ldm_x4(Af[0][1][0],Af[0][1][1],Af[0][1][2],Af[0][1][3], rb[1]);
    ldm_x4(Bf[0][0][0],Bf[0][0][1],Bf[0][0][2],Bf[0][0][3], bt[0]);
    ldm_x4(Bf[0][1][0],Bf[0][1][1],Bf[0][1][2],Bf[0][1][3], bt[1]);

    #pragma unroll
    for (int kk = 0; kk < 27; ++kk) {
        const int cur = kk & 1, nxt = cur ^ 1;
        if (kk < 26) {
            const int k1  = kk + 1;
            const int tap = k1 / 3, ch = k1 - tap*3;
            const int ky  = tap / 3, kx = tap - ky*3;
            const uint32_t po = (uint32_t)((ky*HCOLS + kx)*PXB + ch*32);
            const uint32_t wo = (uint32_t)(tap*96 + ch*32);
            ldm_x4(Af[nxt][0][0],Af[nxt][0][1],Af[nxt][0][2],Af[nxt][0][3], rb[0] + po);
            ldm_x4(Af[nxt][1][0],Af[nxt][1][1],Af[nxt][1][2],Af[nxt][1][3], rb[1] + po);
            ldm_x4(Bf[nxt][0][0],Bf[nxt][0][1],Bf[nxt][0][2],Bf[nxt][0][3], bt[0] + wo);
            ldm_x4(Bf[nxt][1][0],Bf[nxt][1][1],Bf[nxt][1][2],Bf[nxt][1][3], bt[1] + wo);
        }
        #pragma unroll
        for (int si = 0; si < 2; ++si)
            #pragma unroll
            for (int jp = 0; jp < 2; ++jp) {
                mma16816(C[si][2*jp],
                         Af[cur][si][0],Af[cur][si][1],Af[cur][si][2],Af[cur][si][3],
                         Bf[cur][jp][0],Bf[cur][jp][1]);
                mma16816(C[si][2*jp+1],
                         Af[cur][si][0],Af[cur][si][1],Af[cur][si][2],Af[cur][si][3],
                         Bf[cur][jp][2],Bf[cur][jp][3]);
            }
    }

    // epilogue: nh=0 -> z (fp32), nh=1 -> r*h (f16 mirror)
    const int fc  = (lane & 3) * 2;
    const int pxe = lane >> 2;
    const size_t sob = (size_t)(dir*2 + wb)*NPX*FF;
    #pragma unroll
    for (int si = 0; si < 2; ++si)
    #pragma unroll
    for (int cc = 0; cc < 2; ++cc) {
        const int py = 4*rgl + 2*si + cc;
        const int gy = ty0 + py, gx = tx0 + pxe;
        const size_t pb = sob + (size_t)(gy*WW + gx)*FF;
        if (nh == 0) {
            #pragma unroll
            for (int j = 0; j < 4; ++j) {
                const int n = j*8 + fc;
                float v0 = sigm(C[si][j][2*cc]   + __ldg(bias + n));
                float v1 = sigm(C[si][j][2*cc+1] + __ldg(bias + n + 1));
                *(float2*)(g_z + pb + n) = make_float2(v0, v1);
            }
        } else {
            const char* hpx = sHalo + (size_t)(wb*NHALO + (py+1)*HCOLS + (pxe+1))*PXB;
            #pragma unroll
            for (int j = 0; j < 4; ++j) {
                const int n = j*8 + fc;
                float r0 = sigm(C[si][j][2*cc]   + __ldg(bias + 32 + n));
                float r1 = sigm(C[si][j][2*cc+1] + __ldg(bias + 32 + n + 1));
                float2 hv = __half22float2(*(const __half2*)(hpx + n*2));
                *(__half2*)(g_rhf + pb + n) = __floats2half2_rn(r0*hv.x, r1*hv.y);
            }
        }
    }
}

// ---------------- Kernel B: candidate + GRU update (pipelined, r32 x n16) ----------
__global__ void __launch_bounds__(NTHREADS, 1)
stepB(const float* __restrict__ bF, const float* __restrict__ bB,
      float* __restrict__ out, int s)
{
    extern __shared__ char smc[];
    char* sHalo = smc;
    char* sW    = smc + SM_HALO_B;

    const int dir = blockIdx.y, tile = blockIdx.x;
    const int ty0 = (tile / 15) * TILY, tx0 = (tile % 15) * TILX;
    const int t   = dir ? (TT - 1 - s) : s;
    const int tid = threadIdx.x;
    const float* bias = dir ? bB : bF;

    {
        const uint4* src = (const uint4*)(g_wBh + (size_t)dir*32*KW);
        uint4* dst = (uint4*)sW;
        for (int i = tid; i < SM_WB_B/16; i += NTHREADS) dst[i] = src[i];
    }
    stage_halo(sHalo, g_rhf, dir, t, ty0, tx0, tid);
    __syncthreads();

    const int warp = tid >> 5, lane = tid & 31;
    const int rg5 = warp % 10;
    const int nh  = warp / 10;           // n-slice: channels [nh*16, nh*16+16)
    const int wb  = rg5 / 5;
    const int rgl = rg5 % 5;
    const uint32_t haloB = smem_u32(sHalo) + (uint32_t)(wb*NHALO*PXB);
    const uint32_t aHalf = (uint32_t)((lane >> 4) << 4);

    uint32_t rb[2];
    #pragma unroll
    for (int si = 0; si < 2; ++si) {
        int r  = lane & 15;
        int py = 4*rgl + 2*si + (r >> 3);
        int px = r & 7;
        rb[si] = haloB + (uint32_t)((py*HCOLS + px)*PXB) + aHalf;
    }
    const uint32_t wB0 = smem_u32(sW);
    const uint32_t bt = wB0 + (uint32_t)(((nh*16 + (lane>>4)*8 + (lane&7))*WRB))
                           + (uint32_t)(((lane>>3)&1) << 4);

    float C[2][2][4];
    #pragma unroll
    for (int si = 0; si < 2; ++si)
        #pragma unroll
        for (int j = 0; j < 2; ++j)
            C[si][j][0]=C[si][j][1]=C[si][j][2]=C[si][j][3]=0.0f;

    uint32_t Af[2][2][4], Bf[2][4];
    ldm_x4(Af[0][0][0],Af[0][0][1],Af[0][0][2],Af[0][0][3], rb[0]);
    ldm_x4(Af[0][1][0],Af[0][1][1],Af[0][1][2],Af[0][1][3], rb[1]);
    ldm_x4(Bf[0][0],Bf[0][1],Bf[0][2],Bf[0][3], bt);

    #pragma unroll
    for (int kk = 0; kk < 27; ++kk) {
        const int cur = kk & 1, nxt = cur ^ 1;
        if (kk < 26) {
            const int k1  = kk + 1;
            const int tap = k1 / 3, ch = k1 - tap*3;
            const int ky  = tap / 3, kx = tap - ky*3;
            const uint32_t po = (uint32_t)((ky*HCOLS + kx)*PXB + ch*32);
            const uint32_t wo = (uint32_t)(tap*96 + ch*32);
            ldm_x4(Af[nxt][0][0],Af[nxt][0][1],Af[nxt][0][2],Af[nxt][0][3], rb[0] + po);
            ldm_x4(Af[nxt][1][0],Af[nxt][1][1],Af[nxt][1][2],Af[nxt][1][3], rb[1] + po);
            ldm_x4(Bf[nxt][0],Bf[nxt][1],Bf[nxt][2],Bf[nxt][3], bt + wo);
        }
        #pragma unroll
        for (int si = 0; si < 2; ++si) {
            mma16816(C[si][0],
                     Af[cur][si][0],Af[cur][si][1],Af[cur][si][2],Af[cur][si][3],
                     Bf[cur][0],Bf[cur][1]);
            mma16816(C[si][1],
                     Af[cur][si][0],Af[cur][si][1],Af[cur][si][2],Af[cur][si][3],
                     Bf[cur][2],Bf[cur][3]);
        }
    }

    // epilogue: GRU update
    const int fc  = (lane & 3) * 2;
    const int pxe = lane >> 2;
    const size_t sob = (size_t)(dir*2 + wb)*NPX*FF;
    #pragma unroll
    for (int si = 0; si < 2; ++si)
    #pragma unroll
    for (int cc = 0; cc < 2; ++cc) {
        const int py = 4*rgl + 2*si + cc;
        const int gy = ty0 + py, gx = tx0 + pxe;
        const size_t pb = sob + (size_t)(gy*WW + gx)*FF;
        float* op = out + ((size_t)((wb*TT + t)*HH + gy)*WW + gx)*64 + dir*32;
        #pragma unroll
        for (int j = 0; j < 2; ++j) {
            const int n = nh*16 + j*8 + fc;
            float2 z = *(const float2*)(g_z + pb + n);
            float2 h = *(const float2*)(g_h + pb + n);
            float hh0 = ftanh(C[si][j][2*cc]   + __ldg(bias + 64 + n));
            float hh1 = ftanh(C[si][j][2*cc+1] + __ldg(bias + 64 + n + 1));
            float2 hn = make_float2(z.x*h.x + (1.0f - z.x)*hh0,
                                    z.y*h.y + (1.0f - z.y)*hh1);
            *(float2*)(g_h + pb + n)   = hn;
            *(__half2*)(g_hf + pb + n) = __floats2half2_rn(hn.x, hn.y);
            *(float2*)(op + n)         = hn;
        }
    }
}

extern "C" void kernel_launch(void* const* d_in, const int* in_sizes, int n_in,
                              void* d_out, int out_size)
{
    const float* x    = (const float*)d_in[0];
    const float* WxF  = (const float*)d_in[1];
    const float* bF   = (const float*)d_in[2];
    const float* WzrF = (const float*)d_in[3];
    const float* WhF  = (const float*)d_in[4];
    const float* WxB  = (const float*)d_in[5];
    const float* bB   = (const float*)d_in[6];
    const float* WzrB = (const float*)d_in[7];
    const float* WhB  = (const float*)d_in[8];
    float* out = (float*)d_out;

    const int smA = SM_HALO_B + SM_WA_B;   // 105600 B
    const int smB = SM_HALO_B + SM_WB_B;   // 77440 B
    cudaFuncSetAttribute(stepA, cudaFuncAttributeMaxDynamicSharedMemorySize, smA);
    cudaFuncSetAttribute(stepB, cudaFuncAttributeMaxDynamicSharedMemorySize, smB);

    init_kernel<<<148, 512>>>(x, WxF, WzrF, WhF, WxB, WzrB, WhB);

    dim3 grid(NTILES, 2);   // 60 tiles x 2 dir = 120 blocks (single wave, 1/SM)
    for (int s = 0; s < TT; ++s) {
        stepA<<<grid, NTHREADS, smA>>>(bF, bB, s);
        stepB<<<grid, NTHREADS, smB>>>(bF, bB, out, s);
    }
}

// round 17
// speedup vs baseline: 1.3328x; 1.1140x over previous
#include <cuda_runtime.h>
#include <cuda_fp16.h>
#include <cstdint>

// ---------------- problem constants ----------------
#define HH 80
#define WW 120
#define TT 12
#define FF 32
#define NPX (HH*WW)

#define TILY 20
#define TILX 8
#define NTILES 60        // (80/20) * (120/8)
#define NTHREADS 640     // 20 warps: 10 row-groups (5/batch) x 2 n-slices

#define HROWS 22
#define HCOLS 10
#define NHALO 220        // halo pixels per batch
#define PXB 112          // pixel stride bytes: [h 32f16 | x 8f16 | pad]

#define KW 440           // f16 per weight row (432 = 9*48 + pad)
#define WRB 880

#define SM_HALO_B (2*NHALO*PXB)   // 49280
#define SM_WA_B   (64*WRB)        // 56320
#define SM_WB_B   (32*WRB)        // 28160

// ---------------- global scratch ----------------
__device__ __half g_wAh[2*64*KW];
__device__ __half g_wBh[2*32*KW];
__device__ float  g_h  [2*2*NPX*FF];     // fp32 state (exact bypass)
__device__ float  g_z  [2*2*NPX*FF];     // fp32 update gate
__device__ __half g_hf [2*2*NPX*FF];     // f16 mirror (conv operand)
__device__ __half g_rhf[2*2*NPX*FF];     // f16 r*h (conv operand)
__device__ __half g_xf8[2*TT*NPX*8];     // x preconverted (6 + 2 zeros)

// ---------------- helpers ----------------
__device__ __forceinline__ uint32_t smem_u32(const void* p) {
    uint32_t a;
    asm("{ .reg .u64 t; cvta.to.shared.u64 t, %1; cvt.u32.u64 %0, t; }" : "=r"(a) : "l"(p));
    return a;
}
__device__ __forceinline__ float sigm(float v) {
    return __fdividef(1.0f, 1.0f + __expf(-v));
}
__device__ __forceinline__ float ftanh(float v) {
    float e = __expf(-2.0f * v);
    return __fdividef(1.0f - e, 1.0f + e);
}
__device__ __forceinline__ void ldm_x4(uint32_t& r0, uint32_t& r1, uint32_t& r2, uint32_t& r3,
                                       uint32_t addr) {
    asm volatile("ldmatrix.sync.aligned.m8n8.x4.shared.b16 {%0,%1,%2,%3}, [%4];"
                 : "=r"(r0), "=r"(r1), "=r"(r2), "=r"(r3) : "r"(addr));
}
__device__ __forceinline__ void mma16816(float* c,
                                         uint32_t a0, uint32_t a1, uint32_t a2, uint32_t a3,
                                         uint32_t b0, uint32_t b1) {
    asm volatile("mma.sync.aligned.m16n8k16.row.col.f32.f16.f16.f32 "
                 "{%0,%1,%2,%3}, {%4,%5,%6,%7}, {%8,%9}, {%0,%1,%2,%3};"
                 : "+f"(c[0]), "+f"(c[1]), "+f"(c[2]), "+f"(c[3])
                 : "r"(a0), "r"(a1), "r"(a2), "r"(a3), "r"(b0), "r"(b1));
}

// ---------------- merged one-time prologue (weights + x convert + state zero) ------
__global__ void init_kernel(const float* __restrict__ x,
                            const float* __restrict__ WxF, const float* __restrict__ WzrF,
                            const float* __restrict__ WhF,
                            const float* __restrict__ WxB, const float* __restrict__ WzrB,
                            const float* __restrict__ WhB)
{
    const int gstride = gridDim.x * blockDim.x;
    const int gtid = blockIdx.x*blockDim.x + threadIdx.x;

    // 1) weight pack: row n, k = tap*48 + c; c<32 = state ch, 32..37 = x ch, else 0
    {
        const int TOT = 2*96*KW;
        for (int i = gtid; i < TOT; i += gstride) {
            int dir = i / (96*KW); int r = i - dir*(96*KW);
            int n96 = r / KW;      int k = r - n96*KW;
            float v = 0.0f;
            if (k < 432) {
                int tap = k / 48, c = k - tap*48;
                const float* Wx  = dir ? WxB  : WxF;
                const float* Wzr = dir ? WzrB : WzrF;
                const float* Wh  = dir ? WhB  : WhF;
                if (c < 32) {
                    if (n96 < 64) v = Wzr[(tap*32 + c)*64 + n96];
                    else          v = Wh [(tap*32 + c)*32 + (n96 - 64)];
                } else if (c < 38) {
                    v = Wx[(tap*6 + (c - 32))*96 + n96];
                }
            }
            __half hv = __float2half_rn(v);
            if (n96 < 64) g_wAh[(dir*64 + n96)*KW + k]        = hv;
            else          g_wBh[(dir*32 + (n96 - 64))*KW + k] = hv;
        }
    }
    // 2) x -> f16x8 preconvert
    {
        const int n = 2*TT*NPX;
        for (int p = gtid; p < n; p += gstride) {
            const float* src = x + (size_t)p*6;
            __half2 h0 = __floats2half2_rn(src[0], src[1]);
            __half2 h1 = __floats2half2_rn(src[2], src[3]);
            __half2 h2 = __floats2half2_rn(src[4], src[5]);
            uint4 v;
            v.x = *(uint32_t*)&h0; v.y = *(uint32_t*)&h1; v.z = *(uint32_t*)&h2; v.w = 0u;
            *(uint4*)(g_xf8 + (size_t)p*8) = v;
        }
    }
    // 3) zero h (fp32) + hf (f16)
    {
        const int n = 2*2*NPX*FF;
        for (int i = gtid; i < n; i += gstride) {
            g_h[i] = 0.0f;
            if (i < n/2) ((uint32_t*)g_hf)[i] = 0u;
        }
    }
}

// ---------------- halo staging: per-pixel, aligned f16 copies ----------------
__device__ __forceinline__ void stage_halo(char* sHalo, const __half* __restrict__ stf,
                                           int dir, int t, int ty0, int tx0, int tid)
{
    if (tid < 2*NHALO) {
        const int hb  = tid / NHALO;
        const int hpx = tid - hb*NHALO;
        const int sy = hpx / HCOLS, sx = hpx - sy*HCOLS;
        const int gy = ty0 + sy - 1, gx = tx0 + sx - 1;
        uint4* dst = (uint4*)(sHalo + tid*PXB);
        if (gy >= 0 && gy < HH && gx >= 0 && gx < WW) {
            const uint4* hs = (const uint4*)(stf + (size_t)((dir*2 + hb)*NPX + gy*WW + gx)*FF);
            dst[0] = hs[0]; dst[1] = hs[1]; dst[2] = hs[2]; dst[3] = hs[3];
            dst[4] = *(const uint4*)(g_xf8 + (size_t)((hb*TT + t)*NPX + gy*WW + gx)*8);
            dst[5] = make_uint4(0u,0u,0u,0u);
            dst[6] = make_uint4(0u,0u,0u,0u);
        } else {
            uint4 z = make_uint4(0u,0u,0u,0u);
            #pragma unroll
            for (int j = 0; j < 7; ++j) dst[j] = z;
        }
    }
}

// ---------------- Kernel A: gates (pipelined, r32 x n32 per warp) ----------------
__global__ void __launch_bounds__(NTHREADS, 1)
stepA(const float* __restrict__ bF, const float* __restrict__ bB, int s)
{
    extern __shared__ char smc[];
    char* sHalo = smc;
    char* sW    = smc + SM_HALO_B;

    const int dir = blockIdx.y, tile = blockIdx.x;
    const int ty0 = (tile / 15) * TILY, tx0 = (tile % 15) * TILX;
    const int t   = dir ? (TT - 1 - s) : s;
    const int tid = threadIdx.x;
    const float* bias = dir ? bB : bF;

    // independent prologue: weights -> smem (g_wAh is init-time constant)
    {
        const uint4* src = (const uint4*)(g_wAh + (size_t)dir*64*KW);
        uint4* dst = (uint4*)sW;
        for (int i = tid; i < SM_WA_B/16; i += NTHREADS) dst[i] = src[i];
    }
    // allow next kernel to begin its independent prologue; then wait for predecessor
    cudaTriggerProgrammaticLaunchCompletion();
    cudaGridDependencySynchronize();

    stage_halo(sHalo, g_hf, dir, t, ty0, tx0, tid);
    __syncthreads();

    const int warp = tid >> 5, lane = tid & 31;
    const int rg5 = warp % 10;           // row-group (5 per batch)
    const int nh  = warp / 10;           // n-slice: 0 -> z, 1 -> r
    const int wb  = rg5 / 5;             // batch
    const int rgl = rg5 % 5;
    const uint32_t haloB = smem_u32(sHalo) + (uint32_t)(wb*NHALO*PXB);
    const uint32_t aHalf = (uint32_t)((lane >> 4) << 4);

    uint32_t rb[2];
    #pragma unroll
    for (int si = 0; si < 2; ++si) {
        int r  = lane & 15;
        int py = 4*rgl + 2*si + (r >> 3);
        int px = r & 7;
        rb[si] = haloB + (uint32_t)((py*HCOLS + px)*PXB) + aHalf;
    }
    const uint32_t wB0 = smem_u32(sW);
    uint32_t bt[2];
    #pragma unroll
    for (int jp = 0; jp < 2; ++jp)
        bt[jp] = wB0 + (uint32_t)(((nh*32 + jp*16 + (lane>>4)*8 + (lane&7))*WRB))
                     + (uint32_t)(((lane>>3)&1) << 4);

    float C[2][4][4];
    #pragma unroll
    for (int si = 0; si < 2; ++si)
        #pragma unroll
        for (int j = 0; j < 4; ++j)
            C[si][j][0]=C[si][j][1]=C[si][j][2]=C[si][j][3]=0.0f;

    uint32_t Af[2][2][4], Bf[2][2][4];
    ldm_x4(Af[0][0][0],Af[0][0][1],Af[0][0][2],Af[0][0][3], rb[0]);
    ldm_x4(Af[0][1][0],Af[0][1][1],Af[0][1][2],Af[0][1][3], rb[1]);
    ldm_x4(Bf[0][0][0],Bf[0][0][1],Bf[0][0][2],Bf[0][0][3], bt[0]);
    ldm_x4(Bf[0][1][0],Bf[0][1][1],Bf[0][1][2],Bf[0][1][3], bt[1]);

    #pragma unroll
    for (int kk = 0; kk < 27; ++kk) {
        const int cur = kk & 1, nxt = cur ^ 1;
        if (kk < 26) {
            const int k1  = kk + 1;
            const int tap = k1 / 3, ch = k1 - tap*3;
            const int ky  = tap / 3, kx = tap - ky*3;
            const uint32_t po = (uint32_t)((ky*HCOLS + kx)*PXB + ch*32);
            const uint32_t wo = (uint32_t)(tap*96 + ch*32);
            ldm_x4(Af[nxt][0][0],Af[nxt][0][1],Af[nxt][0][2],Af[nxt][0][3], rb[0] + po);
            ldm_x4(Af[nxt][1][0],Af[nxt][1][1],Af[nxt][1][2],Af[nxt][1][3], rb[1] + po);
            ldm_x4(Bf[nxt][0][0],Bf[nxt][0][1],Bf[nxt][0][2],Bf[nxt][0][3], bt[0] + wo);
            ldm_x4(Bf[nxt][1][0],Bf[nxt][1][1],Bf[nxt][1][2],Bf[nxt][1][3], bt[1] + wo);
        }
        #pragma unroll
        for (int si = 0; si < 2; ++si)
            #pragma unroll
            for (int jp = 0; jp < 2; ++jp) {
                mma16816(C[si][2*jp],
                         Af[cur][si][0],Af[cur][si][1],Af[cur][si][2],Af[cur][si][3],
                         Bf[cur][jp][0],Bf[cur][jp][1]);
                mma16816(C[si][2*jp+1],
                         Af[cur][si][0],Af[cur][si][1],Af[cur][si][2],Af[cur][si][3],
                         Bf[cur][jp][2],Bf[cur][jp][3]);
            }
    }

    // epilogue: nh=0 -> z (fp32), nh=1 -> r*h (f16 mirror)
    const int fc  = (lane & 3) * 2;
    const int pxe = lane >> 2;
    const size_t sob = (size_t)(dir*2 + wb)*NPX*FF;
    #pragma unroll
    for (int si = 0; si < 2; ++si)
    #pragma unroll
    for (int cc = 0; cc < 2; ++cc) {
        const int py = 4*rgl + 2*si + cc;
        const int gy = ty0 + py, gx = tx0 + pxe;
        const size_t pb = sob + (size_t)(gy*WW + gx)*FF;
        if (nh == 0) {
            #pragma unroll
            for (int j = 0; j < 4; ++j) {
                const int n = j*8 + fc;
                float v0 = sigm(C[si][j][2*cc]   + __ldg(bias + n));
                float v1 = sigm(C[si][j][2*cc+1] + __ldg(bias + n + 1));
                *(float2*)(g_z + pb + n) = make_float2(v0, v1);
            }
        } else {
            const char* hpx = sHalo + (size_t)(wb*NHALO + (py+1)*HCOLS + (pxe+1))*PXB;
            #pragma unroll
            for (int j = 0; j < 4; ++j) {
                const int n = j*8 + fc;
                float r0 = sigm(C[si][j][2*cc]   + __ldg(bias + 32 + n));
                float r1 = sigm(C[si][j][2*cc+1] + __ldg(bias + 32 + n + 1));
                float2 hv = __half22float2(*(const __half2*)(hpx + n*2));
                *(__half2*)(g_rhf + pb + n) = __floats2half2_rn(r0*hv.x, r1*hv.y);
            }
        }
    }
}

// ---------------- Kernel B: candidate + GRU update (pipelined, r32 x n16) ----------
__global__ void __launch_bounds__(NTHREADS, 1)
stepB(const float* __restrict__ bF, const float* __restrict__ bB,
      float* __restrict__ out, int s)
{
    extern __shared__ char smc[];
    char* sHalo = smc;
    char* sW    = smc + SM_HALO_B;

    const int dir = blockIdx.y, tile = blockIdx.x;
    const int ty0 = (tile / 15) * TILY, tx0 = (tile % 15) * TILX;
    const int t   = dir ? (TT - 1 - s) : s;
    const int tid = threadIdx.x;
    const float* bias = dir ? bB : bF;

    // independent prologue: weights -> smem
    {
        const uint4* src = (const uint4*)(g_wBh + (size_t)dir*32*KW);
        uint4* dst = (uint4*)sW;
        for (int i = tid; i < SM_WB_B/16; i += NTHREADS) dst[i] = src[i];
    }
    cudaTriggerProgrammaticLaunchCompletion();
    cudaGridDependencySynchronize();

    stage_halo(sHalo, g_rhf, dir, t, ty0, tx0, tid);
    __syncthreads();

    const int warp = tid >> 5, lane = tid & 31;
    const int rg5 = warp % 10;
    const int nh  = warp / 10;           // n-slice: channels [nh*16, nh*16+16)
    const int wb  = rg5 / 5;
    const int rgl = rg5 % 5;
    const uint32_t haloB = smem_u32(sHalo) + (uint32_t)(wb*NHALO*PXB);
    const uint32_t aHalf = (uint32_t)((lane >> 4) << 4);

    uint32_t rb[2];
    #pragma unroll
    for (int si = 0; si < 2; ++si) {
        int r  = lane & 15;
        int py = 4*rgl + 2*si + (r >> 3);
        int px = r & 7;
        rb[si] = haloB + (uint32_t)((py*HCOLS + px)*PXB) + aHalf;
    }
    const uint32_t wB0 = smem_u32(sW);
    const uint32_t bt = wB0 + (uint32_t)(((nh*16 + (lane>>4)*8 + (lane&7))*WRB))
                           + (uint32_t)(((lane>>3)&1) << 4);

    float C[2][2][4];
    #pragma unroll
    for (int si = 0; si < 2; ++si)
        #pragma unroll
        for (int j = 0; j < 2; ++j)
            C[si][j][0]=C[si][j][1]=C[si][j][2]=C[si][j][3]=0.0f;

    uint32_t Af[2][2][4], Bf[2][4];
    ldm_x4(Af[0][0][0],Af[0][0][1],Af[0][0][2],Af[0][0][3], rb[0]);
    ldm_x4(Af[0][1][0],Af[0][1][1],Af[0][1][2],Af[0][1][3], rb[1]);
    ldm_x4(Bf[0][0],Bf[0][1],Bf[0][2],Bf[0][3], bt);

    #pragma unroll
    for (int kk = 0; kk < 27; ++kk) {
        const int cur = kk & 1, nxt = cur ^ 1;
        if (kk < 26) {
            const int k1  = kk + 1;
            const int tap = k1 / 3, ch = k1 - tap*3;
            const int ky  = tap / 3, kx = tap - ky*3;
            const uint32_t po = (uint32_t)((ky*HCOLS + kx)*PXB + ch*32);
            const uint32_t wo = (uint32_t)(tap*96 + ch*32);
            ldm_x4(Af[nxt][0][0],Af[nxt][0][1],Af[nxt][0][2],Af[nxt][0][3], rb[0] + po);
            ldm_x4(Af[nxt][1][0],Af[nxt][1][1],Af[nxt][1][2],Af[nxt][1][3], rb[1] + po);
            ldm_x4(Bf[nxt][0],Bf[nxt][1],Bf[nxt][2],Bf[nxt][3], bt + wo);
        }
        #pragma unroll
        for (int si = 0; si < 2; ++si) {
            mma16816(C[si][0],
                     Af[cur][si][0],Af[cur][si][1],Af[cur][si][2],Af[cur][si][3],
                     Bf[cur][0],Bf[cur][1]);
            mma16816(C[si][1],
                     Af[cur][si][0],Af[cur][si][1],Af[cur][si][2],Af[cur][si][3],
                     Bf[cur][2],Bf[cur][3]);
        }
    }

    // epilogue: GRU update
    const int fc  = (lane & 3) * 2;
    const int pxe = lane >> 2;
    const size_t sob = (size_t)(dir*2 + wb)*NPX*FF;
    #pragma unroll
    for (int si = 0; si < 2; ++si)
    #pragma unroll
    for (int cc = 0; cc < 2; ++cc) {
        const int py = 4*rgl + 2*si + cc;
        const int gy = ty0 + py, gx = tx0 + pxe;
        const size_t pb = sob + (size_t)(gy*WW + gx)*FF;
        float* op = out + ((size_t)((wb*TT + t)*HH + gy)*WW + gx)*64 + dir*32;
        #pragma unroll
        for (int j = 0; j < 2; ++j) {
            const int n = nh*16 + j*8 + fc;
            float2 z = *(const float2*)(g_z + pb + n);
            float2 h = *(const float2*)(g_h + pb + n);
            float hh0 = ftanh(C[si][j][2*cc]   + __ldg(bias + 64 + n));
            float hh1 = ftanh(C[si][j][2*cc+1] + __ldg(bias + 64 + n + 1));
            float2 hn = make_float2(z.x*h.x + (1.0f - z.x)*hh0,
                                    z.y*h.y + (1.0f - z.y)*hh1);
            *(float2*)(g_h + pb + n)   = hn;
            *(__half2*)(g_hf + pb + n) = __floats2half2_rn(hn.x, hn.y);
            *(float2*)(op + n)         = hn;
        }
    }
}

extern "C" void kernel_launch(void* const* d_in, const int* in_sizes, int n_in,
                              void* d_out, int out_size)
{
    const float* x    = (const float*)d_in[0];
    const float* WxF  = (const float*)d_in[1];
    const float* bF   = (const float*)d_in[2];
    const float* WzrF = (const float*)d_in[3];
    const float* WhF  = (const float*)d_in[4];
    const float* WxB  = (const float*)d_in[5];
    const float* bB   = (const float*)d_in[6];
    const float* WzrB = (const float*)d_in[7];
    const float* WhB  = (const float*)d_in[8];
    float* out = (float*)d_out;

    const int smA = SM_HALO_B + SM_WA_B;   // 105600 B
    const int smB = SM_HALO_B + SM_WB_B;   // 77440 B
    cudaFuncSetAttribute(stepA, cudaFuncAttributeMaxDynamicSharedMemorySize, smA);
    cudaFuncSetAttribute(stepB, cudaFuncAttributeMaxDynamicSharedMemorySize, smB);

    init_kernel<<<148, 512>>>(x, WxF, WzrF, WhF, WxB, WzrB, WhB);

    dim3 grid(NTILES, 2);   // 60 tiles x 2 dir = 120 blocks (single wave, 1/SM)

    // PDL launch config (programmatic dependent launch on the legacy stream)
    cudaLaunchAttribute pdlAttr[1];
    pdlAttr[0].id = cudaLaunchAttributeProgrammaticStreamSerialization;
    pdlAttr[0].val.programmaticStreamSerializationAllowed = 1;

    cudaLaunchConfig_t cfgA = {};
    cfgA.gridDim = grid; cfgA.blockDim = dim3(NTHREADS, 1, 1);
    cfgA.dynamicSmemBytes = smA; cfgA.stream = 0;
    cfgA.attrs = pdlAttr; cfgA.numAttrs = 1;

    cudaLaunchConfig_t cfgB = cfgA;
    cfgB.dynamicSmemBytes = smB;

    for (int s = 0; s < TT; ++s) {
        if (s == 0) {
            // first stepA must serialize against init_kernel (reads g_wAh in prologue)
            stepA<<<grid, NTHREADS, smA>>>(bF, bB, s);
        } else {
            cudaLaunchKernelEx(&cfgA, stepA, bF, bB, s);
        }
        cudaLaunchKernelEx(&cfgB, stepB, bF, bB, out, s);
    }
}